// round 2
// baseline (speedup 1.0000x reference)
#include <cuda_runtime.h>

#define T_ 1024
#define B_ 128
#define L_ 128

typedef unsigned long long ull;

// scratch (no allocations allowed)
__device__ float g_den[B_];
__device__ float g_num[B_];

__device__ __forceinline__ ull ffma2(ull a, ull b, ull c) {
    ull d;
    asm("fma.rn.f32x2 %0, %1, %2, %3;" : "=l"(d) : "l"(a), "l"(b), "l"(c));
    return d;
}

__device__ __forceinline__ ull pack2(float lo, float hi) {
    ull d;
    asm("mov.b64 %0, {%1, %2};" : "=l"(d) : "f"(lo), "f"(hi));
    return d;
}

__device__ __forceinline__ float2 unpack2(ull v) {
    float2 f;
    asm("mov.b64 {%0, %1}, %2;" : "=f"(f.x), "=f"(f.y) : "l"(v));
    return f;
}

// ---------------------------------------------------------------------------
// Denominator: forward algorithm in linear space with periodic renormalization.
// One block per batch b, one thread per state (column) j.
// u[j] tracks exp(score[j] - logZ); every 4 steps renormalize by block max.
// Inner product over source states i done with packed f32x2 FMA (FFMA2).
// ---------------------------------------------------------------------------
__global__ __launch_bounds__(L_) void crf_den_kernel(
    const float* __restrict__ pred,    // (T,B,L)
    const int*   __restrict__ mask,    // (T,B)
    const float* __restrict__ trans,   // (L,L)
    const float* __restrict__ start,   // (L)
    const float* __restrict__ endv)    // (L)
{
    const int b    = blockIdx.x;
    const int j    = threadIdx.x;
    const int lane = j & 31;
    const int wid  = j >> 5;

    // exp(transitions) column j, packed in pairs over i (64 x 64-bit regs)
    ull rT2[L_ / 2];
#pragma unroll
    for (int k = 0; k < L_ / 2; ++k) {
        float e0 = expf(trans[(2 * k)     * L_ + j]);
        float e1 = expf(trans[(2 * k + 1) * L_ + j]);
        rT2[k] = pack2(e0, e1);
    }

    __shared__ __align__(16) float e_sh[2][L_];
    __shared__ float red[4];

    float u    = __expf(start[j] + pred[b * L_ + j]);  // t = 0
    float logZ = 0.0f;
    int   buf  = 0;
    e_sh[0][j] = u;
    __syncthreads();

    // software-pipelined loads (prediction & mask one step ahead)
    float p  = pred[(size_t)1 * (B_ * L_) + b * L_ + j];
    int   mk = mask[1 * B_ + b];

    for (int t = 1; t < T_; ++t) {
        float p_next  = 0.0f;
        int   mk_next = 0;
        if (t + 1 < T_) {
            p_next  = pred[(size_t)(t + 1) * (B_ * L_) + b * L_ + j];
            mk_next = mask[(t + 1) * B_ + b];
        }

        // acc = sum_i u_prev[i] * expT[i][j]   (broadcast LDS.128 + FFMA2)
        const ulonglong2* ev = reinterpret_cast<const ulonglong2*>(&e_sh[buf][0]);
        ull c0 = 0ull, c1 = 0ull, c2 = 0ull, c3 = 0ull;
#pragma unroll
        for (int i = 0; i < 16; ++i) {
            ulonglong2 x = ev[2 * i];       // u[8i .. 8i+3] as two f32x2
            ulonglong2 y = ev[2 * i + 1];   // u[8i+4 .. 8i+7]
            c0 = ffma2(x.x, rT2[4 * i + 0], c0);
            c1 = ffma2(x.y, rT2[4 * i + 1], c1);
            c2 = ffma2(y.x, rT2[4 * i + 2], c2);
            c3 = ffma2(y.y, rT2[4 * i + 3], c3);
        }
        float2 f0 = unpack2(c0), f1 = unpack2(c1);
        float2 f2 = unpack2(c2), f3 = unpack2(c3);
        float acc = ((f0.x + f0.y) + (f1.x + f1.y)) +
                    ((f2.x + f2.y) + (f3.x + f3.y));

        float u_new = acc * __expf(p);
        u = mk ? u_new : u;

        // renormalize every 4 steps (block max) to keep fp32 in range
        if ((t & 3) == 0) {
            float m = u;
#pragma unroll
            for (int off = 16; off; off >>= 1)
                m = fmaxf(m, __shfl_xor_sync(0xffffffffu, m, off));
            if (lane == 0) red[wid] = m;
            __syncthreads();
            m = fmaxf(fmaxf(red[0], red[1]), fmaxf(red[2], red[3]));
            logZ += logf(m);
            u *= (1.0f / m);
        }

        buf ^= 1;
        e_sh[buf][j] = u;
        __syncthreads();

        p  = p_next;
        mk = mk_next;
    }

    // den[b] = logZ + log( sum_j u[j] * exp(end[j]) )
    float v = u * __expf(endv[j]);
#pragma unroll
    for (int off = 16; off; off >>= 1)
        v += __shfl_xor_sync(0xffffffffu, v, off);
    if (lane == 0) red[wid] = v;
    __syncthreads();
    if (j == 0) {
        float s = (red[0] + red[1]) + (red[2] + red[3]);
        g_den[b] = logZ + logf(s);
    }
}

// ---------------------------------------------------------------------------
// Numerator: path score. One block per batch b, 256 threads stride over t.
// Targets may be int64 (x64 enabled) or int32 (JAX default) — sniff at runtime:
// int64 targets in [0,128) have all-zero high 32-bit words; int32 data viewed
// as word pairs has nonzero odd words with prob 1 - 128^-32.
// ---------------------------------------------------------------------------
__global__ __launch_bounds__(256) void crf_num_kernel(
    const float* __restrict__ pred,
    const void*  __restrict__ tgt_raw,   // (T,B) int64 OR int32
    const int*   __restrict__ mask,
    const float* __restrict__ trans,
    const float* __restrict__ start,
    const float* __restrict__ endv)
{
    const int b    = blockIdx.x;
    const int tid  = threadIdx.x;
    const int lane = tid & 31;
    const int wid  = tid >> 5;

    __shared__ int s_is64;
    if (tid == 0) {
        const unsigned int* w = (const unsigned int*)tgt_raw;
        int is64 = 1;
#pragma unroll
        for (int k = 0; k < 32; ++k)
            if (w[2 * k + 1] != 0u) { is64 = 0; break; }
        s_is64 = is64;
    }
    __syncthreads();
    const int is64 = s_is64;
    const long long* t64 = (const long long*)tgt_raw;
    const int*       t32 = (const int*)tgt_raw;

    float local = 0.0f;
    int   mcnt  = 0;

    for (int t = tid; t < T_; t += 256) {
        const int mk = mask[t * B_ + b];
        mcnt += mk;
        if (t >= 1 && mk) {
            const int cur = is64 ? (int)t64[t * B_ + b]       : t32[t * B_ + b];
            const int prv = is64 ? (int)t64[(t - 1) * B_ + b] : t32[(t - 1) * B_ + b];
            local += trans[prv * L_ + cur] +
                     pred[(size_t)t * (B_ * L_) + b * L_ + cur];
        }
    }

    __shared__ float sf[8];
    __shared__ int   si[8];
#pragma unroll
    for (int off = 16; off; off >>= 1) {
        local += __shfl_xor_sync(0xffffffffu, local, off);
        mcnt  += __shfl_xor_sync(0xffffffffu, mcnt,  off);
    }
    if (lane == 0) { sf[wid] = local; si[wid] = mcnt; }
    __syncthreads();

    if (tid == 0) {
        float tot = 0.0f;
        int   mt  = 0;
#pragma unroll
        for (int w = 0; w < 8; ++w) { tot += sf[w]; mt += si[w]; }
        const int t0 = is64 ? (int)t64[b] : t32[b];   // targets[0, b]
        float s = start[t0] + pred[b * L_ + t0] + tot;
        const int last = mt - 1;
        const int tl = is64 ? (int)t64[last * B_ + b] : t32[last * B_ + b];
        s += endv[tl];
        g_num[b] = s;
    }
}

// ---------------------------------------------------------------------------
// Final: out = mean(den - num)
// ---------------------------------------------------------------------------
__global__ __launch_bounds__(B_) void crf_final_kernel(float* __restrict__ out)
{
    const int j    = threadIdx.x;
    const int lane = j & 31;
    const int wid  = j >> 5;

    float v = g_den[j] - g_num[j];
    __shared__ float red[4];
#pragma unroll
    for (int off = 16; off; off >>= 1)
        v += __shfl_xor_sync(0xffffffffu, v, off);
    if (lane == 0) red[wid] = v;
    __syncthreads();
    if (j == 0)
        out[0] = ((red[0] + red[1]) + (red[2] + red[3])) * (1.0f / (float)B_);
}

extern "C" void kernel_launch(void* const* d_in, const int* in_sizes, int n_in,
                              void* d_out, int out_size)
{
    const float* pred  = (const float*)d_in[0];   // (T,B,L) f32
    const void*  tgt   = (const void*)d_in[1];    // (T,B) i64 or i32
    const int*   mask  = (const int*)d_in[2];     // (T,B) i32
    const float* trans = (const float*)d_in[3];   // (L,L) f32
    const float* start = (const float*)d_in[4];   // (L,) f32
    const float* endv  = (const float*)d_in[5];   // (L,) f32
    float* out = (float*)d_out;

    crf_den_kernel<<<B_, L_>>>(pred, mask, trans, start, endv);
    crf_num_kernel<<<B_, 256>>>(pred, tgt, mask, trans, start, endv);
    crf_final_kernel<<<1, B_>>>(out);
}